// round 1
// baseline (speedup 1.0000x reference)
#include <cuda_runtime.h>
#include <cuda_bf16.h>
#include <cstdint>

// Problem constants
#define C_IN   8
#define C_OUT  16
#define HH     32
#define WW     32
#define N_IN   8192      // C_IN*H*W
#define N_OUT  16384     // C_OUT*OH*OW
#define ROWS   8193      // N_IN + 1
#define COLS   16385     // N_OUT + 1
// M has ROWS*COLS = 134242305 elements; last flat index (8192,16384) handled specially.
#define N4     33560576u // (ROWS*COLS - 1) / 4

#define LOHI_BLOCKS 64
#define M_BLOCKS    1184
#define NTHREADS    256

__global__ __launch_bounds__(NTHREADS)
void conv_abs_kernel(const float* __restrict__ cl,     // concrete_lower, 8192
                     const float* __restrict__ cu,     // concrete_upper, 8192
                     const float* __restrict__ wgt,    // weights, 16*8*3*3 = 1152
                     const float* __restrict__ bias,   // 16
                     float* __restrict__ out)          // lo[16384] | hi[16384] | M[134242305]
{
    __shared__ float s_w[1152];
    __shared__ float s_b[16];
    const int t = threadIdx.x;

    if (blockIdx.x < LOHI_BLOCKS) {
        // ---- lo/hi path: one thread per output pixel (16384 total) ----
        int gid = blockIdx.x * NTHREADS + t;
        int c   = gid >> 10;
        int rem = gid & 1023;
        int i   = rem >> 5;
        int j   = rem & 31;
        // each block spans exactly one output channel c (1024 pixels per c, 256 per block)
        if (t < 72) s_w[t] = wgt[c * 72 + t];
        __syncthreads();

        float accL = bias[c];
        float accH = accL;
        #pragma unroll
        for (int ci = 0; ci < C_IN; ci++) {
            #pragma unroll
            for (int kh = 0; kh < 3; kh++) {
                int y = i - 1 + kh;
                if ((unsigned)y >= 32u) continue;
                #pragma unroll
                for (int kw = 0; kw < 3; kw++) {
                    int x = j - 1 + kw;
                    if ((unsigned)x >= 32u) continue;
                    float w   = s_w[(ci * 3 + kh) * 3 + kw];
                    int   tap = ci * 1024 + y * 32 + x;
                    float l = __ldg(cl + tap);
                    float u = __ldg(cu + tap);
                    accL += w * (w > 0.f ? l : u);
                    accH += w * (w > 0.f ? u : l);
                }
            }
        }
        out[gid]         = accL;   // lo
        out[N_OUT + gid] = accH;   // hi
        return;
    }

    // ---- M fill path: analytic one-pass, float4 stores ----
    for (int k = t; k < 1152; k += NTHREADS) s_w[k] = wgt[k];
    if (t < 16) s_b[t] = bias[t];
    __syncthreads();

    float* __restrict__ M = out + 2 * N_OUT;

    unsigned idx    = (blockIdx.x - LOHI_BLOCKS) * NTHREADS + t;
    const unsigned stride = M_BLOCKS * NTHREADS;

    // last element M[8192, 16384] = 1.0 (not covered by the float4 loop)
    if (blockIdx.x == LOHI_BLOCKS && t == 0) M[(unsigned)ROWS * COLS - 1u] = 1.0f;

    for (; idx < N4; idx += stride) {
        unsigned flat = idx * 4u;
        unsigned r    = flat / 16385u;          // compiler -> umulhi
        unsigned col  = flat - r * 16385u;

        if (r < 8192u && col <= 16380u) {
            // fast path: 4 elements, same row, none is the last column
            unsigned y  = (r >> 5) & 31u;
            unsigned x  = r & 31u;
            unsigned i0 = (col >> 5) & 31u;
            unsigned i3 = ((col + 3u) >> 5) & 31u;
            unsigned d0 = y - i0 + 1u;          // unsigned wrap: valid iff <= 2
            unsigned d3 = y - i3 + 1u;
            float4 v = make_float4(0.f, 0.f, 0.f, 0.f);
            if (d0 <= 2u || d3 <= 2u) {
                unsigned ci = r >> 10;
                float vv[4];
                #pragma unroll
                for (int e = 0; e < 4; e++) {
                    unsigned ce = col + (unsigned)e;
                    unsigned c  = ce >> 10;
                    unsigned i  = (ce >> 5) & 31u;
                    unsigned j  = ce & 31u;
                    unsigned kh = y - i + 1u;
                    unsigned kw = x - j + 1u;
                    bool ok = (kh <= 2u) && (kw <= 2u);
                    unsigned widx = ok ? (((c * 8u + ci) * 3u + kh) * 3u + kw) : 0u;
                    vv[e] = ok ? s_w[widx] : 0.f;
                }
                v = make_float4(vv[0], vv[1], vv[2], vv[3]);
            }
            *reinterpret_cast<float4*>(M + flat) = v;
        } else {
            // slow path: bias row, last column, or row-straddling quad (~0.05% of quads)
            #pragma unroll
            for (int e = 0; e < 4; e++) {
                unsigned f  = flat + (unsigned)e;
                unsigned rr = f / 16385u;
                unsigned cc = f - rr * 16385u;
                float v;
                if (rr == 8192u) {
                    v = (cc == 16384u) ? 1.0f : s_b[cc >> 10];
                } else if (cc == 16384u) {
                    v = 0.f;
                } else {
                    unsigned ci = rr >> 10;
                    unsigned y  = (rr >> 5) & 31u;
                    unsigned x  = rr & 31u;
                    unsigned c  = cc >> 10;
                    unsigned i  = (cc >> 5) & 31u;
                    unsigned j  = cc & 31u;
                    unsigned kh = y - i + 1u;
                    unsigned kw = x - j + 1u;
                    bool ok = (kh <= 2u) && (kw <= 2u);
                    v = ok ? s_w[((c * 8u + ci) * 3u + kh) * 3u + kw] : 0.f;
                }
                M[f] = v;
            }
        }
    }
}

extern "C" void kernel_launch(void* const* d_in, const int* in_sizes, int n_in,
                              void* d_out, int out_size) {
    const float* cl   = (const float*)d_in[0];
    const float* cu   = (const float*)d_in[1];
    const float* wgt  = (const float*)d_in[2];
    const float* bias = (const float*)d_in[3];
    float* out = (float*)d_out;

    conv_abs_kernel<<<LOHI_BLOCKS + M_BLOCKS, NTHREADS>>>(cl, cu, wgt, bias, out);
}

// round 2
// speedup vs baseline: 1.1004x; 1.1004x over previous
#include <cuda_runtime.h>
#include <cuda_bf16.h>
#include <cstdint>

// Problem constants
#define C_IN   8
#define C_OUT  16
#define N_IN   8192      // C_IN*32*32
#define N_OUT  16384     // C_OUT*32*32
#define ROWS   8193      // N_IN + 1
#define COLS   16385     // N_OUT + 1

#define LOHI_BLOCKS 64
#define NTHREADS    256

__global__ __launch_bounds__(NTHREADS)
void conv_abs_kernel(const float* __restrict__ cl,     // concrete_lower, 8192
                     const float* __restrict__ cu,     // concrete_upper, 8192
                     const float* __restrict__ wgt,    // weights, 16*8*3*3 = 1152
                     const float* __restrict__ bias,   // 16
                     float* __restrict__ out)          // lo[16384] | hi[16384] | M[8193*16385]
{
    const int t = threadIdx.x;

    if (blockIdx.x < LOHI_BLOCKS) {
        // ---- lo/hi path: one thread per output pixel (16384 total) ----
        __shared__ float s_w[72];
        int gid = blockIdx.x * NTHREADS + t;
        int c   = gid >> 10;
        int rem = gid & 1023;
        int i   = rem >> 5;
        int j   = rem & 31;
        if (t < 72) s_w[t] = wgt[c * 72 + t];   // block spans exactly one channel c
        __syncthreads();

        float accL = bias[c];
        float accH = accL;
        #pragma unroll
        for (int ci = 0; ci < C_IN; ci++) {
            #pragma unroll
            for (int kh = 0; kh < 3; kh++) {
                int y = i - 1 + kh;
                if ((unsigned)y >= 32u) continue;
                #pragma unroll
                for (int kw = 0; kw < 3; kw++) {
                    int x = j - 1 + kw;
                    if ((unsigned)x >= 32u) continue;
                    float w   = s_w[(ci * 3 + kh) * 3 + kw];
                    int   tap = ci * 1024 + y * 32 + x;
                    float l = __ldg(cl + tap);
                    float u = __ldg(cu + tap);
                    accL += w * (w > 0.f ? l : u);
                    accH += w * (w > 0.f ? u : l);
                }
            }
        }
        out[gid]         = accL;   // lo
        out[N_OUT + gid] = accH;   // hi
        return;
    }

    // ---- M fill: one block per row, two-phase (zero-stream, then patch) ----
    float* __restrict__ M = out + 2 * N_OUT;

    const unsigned r = blockIdx.x - LOHI_BLOCKS;        // 0..8192
    const size_t   base = (size_t)r * (size_t)COLS;     // element offset of row start
    float* __restrict__ row = M + base;

    const float4 z4 = make_float4(0.f, 0.f, 0.f, 0.f);

    if (r < 8192u) {
        // Phase 1: stream zeros over the whole row (65540 B).
        const unsigned p     = (4u - (r & 3u)) & 3u;    // peel to 16B alignment
        const unsigned quads = (16384u - p) >> 2;       // 4096 (p=0) or 4095
        if (t < (int)p) row[t] = 0.f;
        float* __restrict__ ali = row + p;
        #pragma unroll 4
        for (unsigned q = t; q < quads; q += NTHREADS)
            *reinterpret_cast<float4*>(ali + 4u * q) = z4;
        const unsigned tail_start = p + 4u * quads;
        const unsigned ntail = (unsigned)COLS - tail_start;  // 1..4 (covers last col too)
        if (t < (int)ntail) row[tail_start + t] = 0.f;

        __syncthreads();  // order phase-1 global stores before phase-2 overwrites

        // Phase 2: patch the 144 nonzeros of this row. Row r = (ci, y, x).
        if (t < 144) {
            const unsigned ci  = r >> 10;
            const unsigned y   = (r >> 5) & 31u;
            const unsigned x   = r & 31u;
            const unsigned c   = (unsigned)t / 9u;
            const unsigned rem = (unsigned)t - c * 9u;
            const unsigned dy  = rem / 3u;
            const unsigned dx  = rem - dy * 3u;
            const int i = (int)y - 1 + (int)dy;
            const int j = (int)x - 1 + (int)dx;
            if ((unsigned)i < 32u && (unsigned)j < 32u) {
                const unsigned kh  = 2u - dy;
                const unsigned kw  = 2u - dx;
                const unsigned col = c * 1024u + (unsigned)i * 32u + (unsigned)j;
                row[col] = __ldg(wgt + ((c * 8u + ci) * 3u + kh) * 3u + kw);
            }
        }
    } else {
        // Bias row r == 8192: base is 16B-aligned (8192*16385 % 4 == 0).
        #pragma unroll 4
        for (unsigned q = t; q < 4096u; q += NTHREADS) {
            const unsigned col = 4u * q;
            const float b = __ldg(bias + (col >> 10));
            *reinterpret_cast<float4*>(row + col) = make_float4(b, b, b, b);
        }
        if (t == 0) row[16384] = 1.0f;
    }
}

extern "C" void kernel_launch(void* const* d_in, const int* in_sizes, int n_in,
                              void* d_out, int out_size) {
    const float* cl   = (const float*)d_in[0];
    const float* cu   = (const float*)d_in[1];
    const float* wgt  = (const float*)d_in[2];
    const float* bias = (const float*)d_in[3];
    float* out = (float*)d_out;

    conv_abs_kernel<<<LOHI_BLOCKS + ROWS, NTHREADS>>>(cl, cu, wgt, bias, out);
}